// round 2
// baseline (speedup 1.0000x reference)
#include <cuda_runtime.h>

#define SEQ    2048
#define NB     2
#define DIM    1024
#define NH     16
#define DH     64
#define TOKENS (NB*SEQ)
#define AST    68   // padded smem row stride (floats) for attention tiles

// Scratch (allocation-free): projected q/k/v and attention output, [4096,1024] row-major.
__device__ float g_q[TOKENS*DIM];
__device__ float g_k[TOKENS*DIM];
__device__ float g_v[TOKENS*DIM];
__device__ float g_att[TOKENS*DIM];

// ---------------------------------------------------------------------------
// C[M,N] = A[M,K] @ W[N,K]^T   (M=4096, N=K=1024)
// 128x128 block tile, BK=16, 256 threads, 8x8 per-thread microtile.
// Smem stored k-major (transposed) so the inner loop is pure float4 LDS.
// ---------------------------------------------------------------------------
__device__ __forceinline__ void gemm_body(const float* __restrict__ A,
                                          const float* __restrict__ W,
                                          float* __restrict__ C,
                                          int m0, int n0)
{
    __shared__ float As[16][132];
    __shared__ float Bs[16][132];
    const int K = DIM, N = DIM;
    const int tid = threadIdx.x;
    const int tx = tid & 15, ty = tid >> 4;

    float acc[8][8];
#pragma unroll
    for (int i = 0; i < 8; i++)
#pragma unroll
        for (int j = 0; j < 8; j++) acc[i][j] = 0.f;

    for (int k0 = 0; k0 < K; k0 += 16) {
#pragma unroll
        for (int l = 0; l < 2; l++) {
            int idx = tid + l * 256;          // 0..511 float4 slots
            int row = idx >> 2;               // 0..127
            int kk  = (idx & 3) << 2;         // 0,4,8,12
            float4 a = *(const float4*)&A[(m0 + row) * K + k0 + kk];
            As[kk+0][row] = a.x; As[kk+1][row] = a.y;
            As[kk+2][row] = a.z; As[kk+3][row] = a.w;
            float4 b = *(const float4*)&W[(n0 + row) * K + k0 + kk];
            Bs[kk+0][row] = b.x; Bs[kk+1][row] = b.y;
            Bs[kk+2][row] = b.z; Bs[kk+3][row] = b.w;
        }
        __syncthreads();
#pragma unroll
        for (int kk = 0; kk < 16; kk++) {
            float a[8], b[8];
            *(float4*)&a[0] = *(const float4*)&As[kk][ty * 8];
            *(float4*)&a[4] = *(const float4*)&As[kk][ty * 8 + 4];
            *(float4*)&b[0] = *(const float4*)&Bs[kk][tx * 8];
            *(float4*)&b[4] = *(const float4*)&Bs[kk][tx * 8 + 4];
#pragma unroll
            for (int i = 0; i < 8; i++)
#pragma unroll
                for (int j = 0; j < 8; j++)
                    acc[i][j] = fmaf(a[i], b[j], acc[i][j]);
        }
        __syncthreads();
    }
#pragma unroll
    for (int i = 0; i < 8; i++) {
        int m = m0 + ty * 8 + i;
        *(float4*)&C[m * N + n0 + tx * 8] =
            make_float4(acc[i][0], acc[i][1], acc[i][2], acc[i][3]);
        *(float4*)&C[m * N + n0 + tx * 8 + 4] =
            make_float4(acc[i][4], acc[i][5], acc[i][6], acc[i][7]);
    }
}

__global__ __launch_bounds__(256, 2)
void gemm_awt(const float* __restrict__ A, const float* __restrict__ W,
              float* __restrict__ C)
{
    gemm_body(A, W, C, blockIdx.y * 128, blockIdx.x * 128);
}

// Fused Q/K/V projections: grid.z selects which of the three GEMMs.
__global__ __launch_bounds__(256, 2)
void proj3(const float* __restrict__ Q, const float* __restrict__ Kin,
           const float* __restrict__ V,
           const float* __restrict__ Wq, const float* __restrict__ Wk,
           const float* __restrict__ Wv,
           float* __restrict__ gq, float* __restrict__ gk, float* __restrict__ gv)
{
    const float* A; const float* W; float* C;
    if (blockIdx.z == 0)      { A = Q;   W = Wq; C = gq; }
    else if (blockIdx.z == 1) { A = Kin; W = Wk; C = gk; }
    else                      { A = V;   W = Wv; C = gv; }
    gemm_body(A, W, C, blockIdx.y * 128, blockIdx.x * 128);
}

// ---------------------------------------------------------------------------
// Attention: one block per (q-tile of 64, head, batch).
// Faithful softmax: clamp(score/8, +-50) -> exp -> rowsum (-> 1 if <=0) -> div.
// No max-subtraction in the reference, so streaming accumulation is exact.
// ---------------------------------------------------------------------------
__global__ __launch_bounds__(256)
void attn_kernel(const float* __restrict__ Qp, const float* __restrict__ Kp,
                 const float* __restrict__ Vp,
                 const int* __restrict__ mask,
                 float* __restrict__ Op)
{
    extern __shared__ float sm[];
    float* qs = sm;               // [64][AST] transposed: qs[d*AST + m]
    float* ks = qs + 64 * AST;    // [64][AST] transposed: ks[d*AST + n]
    float* vs = ks + 64 * AST;    // [64][AST] natural:    vs[key*AST + d]
    float* ps = vs + 64 * AST;    // [64][AST] natural:    ps[m*AST + j]

    const int tid = threadIdx.x;
    const int tx = tid & 15, ty = tid >> 4;
    const int q0 = blockIdx.x * 64;
    const int h  = blockIdx.y;
    const int b  = blockIdx.z;

    const float* qb = Qp + (b * SEQ) * DIM + h * DH;
    const float* kb = Kp + (b * SEQ) * DIM + h * DH;
    const float* vb = Vp + (b * SEQ) * DIM + h * DH;

    // Load Q tile (64 rows x 64 d), store transposed for float4 reads over d.
#pragma unroll
    for (int l = 0; l < 4; l++) {
        int idx = tid + l * 256;        // 0..1023
        int row = idx >> 4;             // 0..63
        int d4  = (idx & 15) << 2;      // 0..60
        float4 a = *(const float4*)&qb[(q0 + row) * DIM + d4];
        qs[(d4+0)*AST + row] = a.x; qs[(d4+1)*AST + row] = a.y;
        qs[(d4+2)*AST + row] = a.z; qs[(d4+3)*AST + row] = a.w;
    }

    float mrow[4];
#pragma unroll
    for (int i = 0; i < 4; i++)
        mrow[i] = mask[b * SEQ + q0 + ty * 4 + i] ? 1.f : 0.f;

    float o[4][4], denom[4];
#pragma unroll
    for (int i = 0; i < 4; i++) {
        denom[i] = 0.f;
#pragma unroll
        for (int j = 0; j < 4; j++) o[i][j] = 0.f;
    }
    __syncthreads();

    for (int t = 0; t < SEQ / 64; t++) {
        const int k0 = t * 64;
        // Load K tile (transposed) and V tile (natural).
#pragma unroll
        for (int l = 0; l < 4; l++) {
            int idx = tid + l * 256;
            int row = idx >> 4;
            int d4  = (idx & 15) << 2;
            float4 kv = *(const float4*)&kb[(k0 + row) * DIM + d4];
            ks[(d4+0)*AST + row] = kv.x; ks[(d4+1)*AST + row] = kv.y;
            ks[(d4+2)*AST + row] = kv.z; ks[(d4+3)*AST + row] = kv.w;
            float4 vv = *(const float4*)&vb[(k0 + row) * DIM + d4];
            *(float4*)&vs[row * AST + d4] = vv;
        }
        __syncthreads();

        // S = Q * K^T (4x4 microtile per thread)
        float s[4][4];
#pragma unroll
        for (int i = 0; i < 4; i++)
#pragma unroll
            for (int j = 0; j < 4; j++) s[i][j] = 0.f;
#pragma unroll 16
        for (int d = 0; d < 64; d++) {
            float qa[4], ka[4];
            *(float4*)qa = *(const float4*)&qs[d * AST + ty * 4];
            *(float4*)ka = *(const float4*)&ks[d * AST + tx * 4];
#pragma unroll
            for (int i = 0; i < 4; i++)
#pragma unroll
                for (int j = 0; j < 4; j++)
                    s[i][j] = fmaf(qa[i], ka[j], s[i][j]);
        }

        // P = exp(clamp(S/8)) * query-mask ; accumulate partial row sums.
#pragma unroll
        for (int i = 0; i < 4; i++)
#pragma unroll
            for (int j = 0; j < 4; j++) {
                float sc = s[i][j] * 0.125f;
                sc = fminf(fmaxf(sc, -50.f), 50.f);
                float p = __expf(sc) * mrow[i];
                denom[i] += p;
                ps[(ty * 4 + i) * AST + tx * 4 + j] = p;
            }
        __syncthreads();

        // O += P * V
#pragma unroll 16
        for (int j = 0; j < 64; j++) {
            float vv[4];
            *(float4*)vv = *(const float4*)&vs[j * AST + tx * 4];
#pragma unroll
            for (int i = 0; i < 4; i++) {
                float p = ps[(ty * 4 + i) * AST + j];
#pragma unroll
                for (int c = 0; c < 4; c++)
                    o[i][c] = fmaf(p, vv[c], o[i][c]);
            }
        }
        __syncthreads();
    }

    // Row-sum reduce across tx (lanes differing in bits 0..3 only).
#pragma unroll
    for (int i = 0; i < 4; i++) {
#pragma unroll
        for (int m = 1; m < 16; m <<= 1)
            denom[i] += __shfl_xor_sync(0xffffffffu, denom[i], m);
        float dn = denom[i];
        if (dn <= 0.f) dn = 1.f;               // reference safe-denominator
        float inv = 1.f / dn;
        int row = q0 + ty * 4 + i;
        *(float4*)&Op[(b * SEQ + row) * DIM + h * DH + tx * 4] =
            make_float4(o[i][0] * inv, o[i][1] * inv, o[i][2] * inv, o[i][3] * inv);
    }
}

// ---------------------------------------------------------------------------
extern "C" void kernel_launch(void* const* d_in, const int* in_sizes, int n_in,
                              void* d_out, int out_size)
{
    const float* Q  = (const float*)d_in[0];
    const float* K  = (const float*)d_in[1];
    const float* V  = (const float*)d_in[2];
    const int*   mask = (const int*)d_in[3];   // bool mask materialized as int32
    const float* Wq = (const float*)d_in[4];
    const float* Wk = (const float*)d_in[5];
    const float* Wv = (const float*)d_in[6];
    const float* Wo = (const float*)d_in[7];
    float* out = (float*)d_out;

    float *gq, *gk, *gv, *ga;
    cudaGetSymbolAddress((void**)&gq, g_q);
    cudaGetSymbolAddress((void**)&gk, g_k);
    cudaGetSymbolAddress((void**)&gv, g_v);
    cudaGetSymbolAddress((void**)&ga, g_att);

    const int ATTN_SMEM = 4 * 64 * AST * (int)sizeof(float);   // 69632 B
    cudaFuncSetAttribute(attn_kernel,
                         cudaFuncAttributeMaxDynamicSharedMemorySize, ATTN_SMEM);

    dim3 pg(DIM / 128, TOKENS / 128, 3);        // 8 x 32 x 3
    proj3<<<pg, 256>>>(Q, K, V, Wq, Wk, Wv, gq, gk, gv);

    dim3 ag(SEQ / 64, NH, NB);                  // 32 x 16 x 2
    attn_kernel<<<ag, 256, ATTN_SMEM>>>(gq, gk, gv, mask, ga);

    dim3 gg(DIM / 128, TOKENS / 128);           // 8 x 32
    gemm_awt<<<gg, 256>>>(ga, Wo, out);
}

// round 17
// speedup vs baseline: 2.0432x; 2.0432x over previous
#include <cuda_runtime.h>
#include <cuda_bf16.h>
#include <cstdint>

#define SEQ    2048
#define NB     2
#define DIM    1024
#define NH     16
#define DH     64
#define TOKENS (NB*SEQ)
#define ND     (TOKENS*DIM)
#define DD     (DIM*DIM)

// fp32 scratch
__device__ float g_q[ND];
__device__ float g_k[ND];
__device__ float g_v[ND];
__device__ float g_att[ND];
// bf16 hi/lo split scratch
__device__ __nv_bfloat16 g_xh[3*ND], g_xl[3*ND];     // inputs, later split q/k
__device__ __nv_bfloat16 g_wh[4*DD], g_wl[4*DD];     // Wq,Wk,Wv,Wo
__device__ __nv_bfloat16 g_ath[ND],  g_atl[ND];      // attention output split

// ---------------------------------------------------------------------------
// Base-sm_103-legal primitives: mma.sync / ldmatrix / cp.async  (NO tcgen05)
// ---------------------------------------------------------------------------
__device__ __forceinline__ uint32_t smem_u32(const void* p) {
    uint32_t a;
    asm("{ .reg .u64 t; cvta.to.shared.u64 t, %1; cvt.u32.u64 %0, t; }"
        : "=r"(a) : "l"(p));
    return a;
}
__device__ __forceinline__ void cpa16(uint32_t sa, const void* g) {
    asm volatile("cp.async.cg.shared.global [%0], [%1], 16;" :: "r"(sa), "l"(g));
}
__device__ __forceinline__ void ldsm4(uint32_t* r, uint32_t addr) {
    asm volatile("ldmatrix.sync.aligned.m8n8.x4.shared.b16 {%0,%1,%2,%3}, [%4];"
        : "=r"(r[0]), "=r"(r[1]), "=r"(r[2]), "=r"(r[3]) : "r"(addr));
}
__device__ __forceinline__ void mma16816(float* c, const uint32_t* a,
                                         uint32_t b0, uint32_t b1) {
    asm volatile("mma.sync.aligned.m16n8k16.row.col.f32.bf16.bf16.f32 "
        "{%0,%1,%2,%3}, {%4,%5,%6,%7}, {%8,%9}, {%0,%1,%2,%3};"
        : "+f"(c[0]), "+f"(c[1]), "+f"(c[2]), "+f"(c[3])
        : "r"(a[0]), "r"(a[1]), "r"(a[2]), "r"(a[3]), "r"(b0), "r"(b1));
}

// 64B-row tile (32 bf16/row), chunk swizzle — used by tc_gemm.
__device__ __forceinline__ uint32_t tile_off(int r, int ch) {
    return (uint32_t)(r * 64 + (((ch ^ ((r >> 1) & 3))) << 4));
}
__device__ __forceinline__ uint32_t ldsm_addr(uint32_t tb, int R, int ks8, int lane) {
    int mi = lane >> 3, lr = lane & 7;
    int row = R + ((mi & 1) << 3) + lr;
    int ch  = ks8 + (mi >> 1);
    return tb + tile_off(row, ch);
}
// 128B-row tile (64 bf16/row), XOR-8 chunk swizzle — used by attn_mma.
__device__ __forceinline__ uint32_t off64(int r, int ch) {
    return (uint32_t)(r * 128 + ((ch ^ (r & 7)) << 4));
}
__device__ __forceinline__ uint32_t ldsm_addr64(uint32_t tb, int R, int ks8, int lane) {
    int mi = lane >> 3, lr = lane & 7;
    int row = R + ((mi & 1) << 3) + lr;
    int ch  = ks8 + (mi >> 1);
    return tb + off64(row, ch);
}

// ---------------------------------------------------------------------------
// fp32 -> bf16 hi/lo split.
// ---------------------------------------------------------------------------
__global__ void conv4(const float* __restrict__ a, const float* __restrict__ b,
                      const float* __restrict__ c, const float* __restrict__ d,
                      __nv_bfloat16* __restrict__ hi, __nv_bfloat16* __restrict__ lo,
                      int n_per)
{
    const float* src = (blockIdx.z == 0) ? a : (blockIdx.z == 1) ? b
                     : (blockIdx.z == 2) ? c : d;
    size_t base = (size_t)blockIdx.z * n_per;
    size_t i = ((size_t)blockIdx.x * blockDim.x + threadIdx.x) * 4;
    float4 x = *(const float4*)(src + i);
    __nv_bfloat16 h0 = __float2bfloat16_rn(x.x);
    __nv_bfloat16 h1 = __float2bfloat16_rn(x.y);
    __nv_bfloat16 h2 = __float2bfloat16_rn(x.z);
    __nv_bfloat16 h3 = __float2bfloat16_rn(x.w);
    __nv_bfloat16 l0 = __float2bfloat16_rn(x.x - __bfloat162float(h0));
    __nv_bfloat16 l1 = __float2bfloat16_rn(x.y - __bfloat162float(h1));
    __nv_bfloat16 l2 = __float2bfloat16_rn(x.z - __bfloat162float(h2));
    __nv_bfloat16 l3 = __float2bfloat16_rn(x.w - __bfloat162float(h3));
    *(__nv_bfloat162*)(hi + base + i)     = __halves2bfloat162(h0, h1);
    *(__nv_bfloat162*)(hi + base + i + 2) = __halves2bfloat162(h2, h3);
    *(__nv_bfloat162*)(lo + base + i)     = __halves2bfloat162(l0, l1);
    *(__nv_bfloat162*)(lo + base + i + 2) = __halves2bfloat162(l2, l3);
}

// ---------------------------------------------------------------------------
// Split-bf16 GEMM on mma.sync: C[4096,1024] = A @ W^T (3-term split).
// ---------------------------------------------------------------------------
#define STG 32768
#define GEMM_SMEM (2*STG)

__device__ __forceinline__ void load_stage(
    uint32_t sb, int stage, int kc, int m0, int n0,
    const __nv_bfloat16* Ah, const __nv_bfloat16* Al,
    const __nv_bfloat16* Wh, const __nv_bfloat16* Wl, int tid)
{
    uint32_t stb = sb + stage * STG;
#pragma unroll
    for (int it = 0; it < 8; it++) {
        int idx  = tid + it * 256;
        int tile = idx >> 9;
        int rc   = idx & 511;
        int r    = rc >> 2, c2 = rc & 3;
        const __nv_bfloat16* src = (tile == 0) ? Ah : (tile == 1) ? Al
                                 : (tile == 2) ? Wh : Wl;
        int grow = ((tile < 2) ? m0 : n0) + r;
        cpa16(stb + tile * 8192u + tile_off(r, c2),
              src + (size_t)grow * DIM + kc + c2 * 8);
    }
    asm volatile("cp.async.commit_group;" ::: "memory");
}

__global__ __launch_bounds__(256, 1)
void tc_gemm(const __nv_bfloat16* __restrict__ Ah, const __nv_bfloat16* __restrict__ Al,
             const __nv_bfloat16* __restrict__ Wh, const __nv_bfloat16* __restrict__ Wl,
             float* __restrict__ C0, float* __restrict__ C1, float* __restrict__ C2)
{
    extern __shared__ char smem[];
    const int z = blockIdx.z;
    Ah += (size_t)z * ND; Al += (size_t)z * ND;
    Wh += (size_t)z * DD; Wl += (size_t)z * DD;
    float* C = (z == 0) ? C0 : (z == 1) ? C1 : C2;
    const int m0 = blockIdx.y * 128, n0 = blockIdx.x * 128;
    const int tid = threadIdx.x, wid = tid >> 5, lane = tid & 31;
    const int wm = (wid & 3) * 32;
    const int wn = (wid >> 2) * 64;
    uint32_t sb = smem_u32(smem);

    float acc[2][8][4];
#pragma unroll
    for (int m = 0; m < 2; m++)
#pragma unroll
        for (int j = 0; j < 8; j++)
#pragma unroll
            for (int q = 0; q < 4; q++) acc[m][j][q] = 0.f;

    load_stage(sb, 0, 0, m0, n0, Ah, Al, Wh, Wl, tid);

    for (int kt = 0; kt < 32; kt++) {
        if (kt + 1 < 32) {
            load_stage(sb, (kt + 1) & 1, (kt + 1) * 32, m0, n0, Ah, Al, Wh, Wl, tid);
            asm volatile("cp.async.wait_group 1;" ::: "memory");
        } else {
            asm volatile("cp.async.wait_group 0;" ::: "memory");
        }
        __syncthreads();

        uint32_t stb = sb + (kt & 1) * STG;
#pragma unroll
        for (int ks8 = 0; ks8 < 4; ks8 += 2) {
            uint32_t ah[2][4], al[2][4], wh[4][4], wl[4][4];
#pragma unroll
            for (int m = 0; m < 2; m++) {
                ldsm4(ah[m], ldsm_addr(stb,          wm + m * 16, ks8, lane));
                ldsm4(al[m], ldsm_addr(stb + 8192u,  wm + m * 16, ks8, lane));
            }
#pragma unroll
            for (int g = 0; g < 4; g++) {
                ldsm4(wh[g], ldsm_addr(stb + 16384u, wn + g * 16, ks8, lane));
                ldsm4(wl[g], ldsm_addr(stb + 24576u, wn + g * 16, ks8, lane));
            }
#pragma unroll
            for (int m = 0; m < 2; m++)
#pragma unroll
                for (int j = 0; j < 8; j++) {
                    int g = j >> 1, hi = j & 1;
                    mma16816(acc[m][j], ah[m], wh[g][hi], wh[g][2 + hi]);
                    mma16816(acc[m][j], ah[m], wl[g][hi], wl[g][2 + hi]);
                    mma16816(acc[m][j], al[m], wh[g][hi], wh[g][2 + hi]);
                }
        }
        __syncthreads();
    }

    const int r0 = m0 + wm + (lane >> 2);
    const int cb = n0 + wn + (lane & 3) * 2;
#pragma unroll
    for (int m = 0; m < 2; m++) {
#pragma unroll
        for (int j = 0; j < 8; j++) {
            int row = r0 + m * 16;
            *(float2*)&C[(size_t)row * DIM + cb + j * 8] =
                make_float2(acc[m][j][0], acc[m][j][1]);
            *(float2*)&C[(size_t)(row + 8) * DIM + cb + j * 8] =
                make_float2(acc[m][j][2], acc[m][j][3]);
        }
    }
}

// ---------------------------------------------------------------------------
// Attention on mma.sync, split-bf16 for BOTH QK^T and PV.
// One CTA per (64 queries, head, batch); 8 warps in 4x2 (wm 16, wn 32).
// Smem: qh ql kh kl vh vl ph pl (8KB each, off64 layout) + pden + mask.
// ---------------------------------------------------------------------------
#define ATT_SMEM (65536 + 768)

__global__ __launch_bounds__(256)
void attn_mma(const __nv_bfloat16* __restrict__ xh, const __nv_bfloat16* __restrict__ xl,
              const float* __restrict__ Vp, const int* __restrict__ mask,
              float* __restrict__ Op)
{
    extern __shared__ char smem[];
    uint32_t sb = smem_u32(smem);
    const uint32_t qh = sb,          ql = sb + 8192;
    const uint32_t kh = sb + 16384,  kl = sb + 24576;
    const uint32_t vh = sb + 32768,  vl = sb + 40960;
    const uint32_t ph = sb + 49152,  pl = sb + 57344;
    float* pden = (float*)(smem + 65536);        // [2][64]
    float* mk   = (float*)(smem + 65536 + 512);  // [64]

    const int tid = threadIdx.x, wid = tid >> 5, lane = tid & 31;
    const int q0 = blockIdx.x * 64, h = blockIdx.y, b = blockIdx.z;
    const int wm = (wid & 3) * 16, wn = (wid >> 2) * 32;

    const __nv_bfloat16* qgh = xh + (size_t)(b * SEQ + q0) * DIM + h * DH;
    const __nv_bfloat16* qgl = xl + (size_t)(b * SEQ + q0) * DIM + h * DH;
    const __nv_bfloat16* kgh = xh + (size_t)ND + (size_t)(b * SEQ) * DIM + h * DH;
    const __nv_bfloat16* kgl = xl + (size_t)ND + (size_t)(b * SEQ) * DIM + h * DH;

    // Q tiles (persistent) via cp.async.
#pragma unroll
    for (int i = tid; i < 512; i += 256) {
        int r = i >> 3, ch = i & 7;
        cpa16(qh + off64(r, ch), qgh + (size_t)r * DIM + ch * 8);
        cpa16(ql + off64(r, ch), qgl + (size_t)r * DIM + ch * 8);
    }
    asm volatile("cp.async.commit_group;" ::: "memory");
    if (tid < 64) mk[tid] = mask[b * SEQ + q0 + tid] ? 1.f : 0.f;

    float o[4][4];
#pragma unroll
    for (int j = 0; j < 4; j++)
#pragma unroll
        for (int q = 0; q < 4; q++) o[j][q] = 0.f;
    float dacc1 = 0.f, dacc2 = 0.f;

    asm volatile("cp.async.wait_group 0;" ::: "memory");
    __syncthreads();
    const int r1 = wm + (lane >> 2), r2 = r1 + 8;
    const float m1 = mk[r1], m2 = mk[r2];

    for (int t = 0; t < SEQ / 64; t++) {
        const int k0 = t * 64;
        __syncthreads();   // prior iteration's mma reads complete

        // K tiles via cp.async.
#pragma unroll
        for (int i = tid; i < 512; i += 256) {
            int r = i >> 3, ch = i & 7;
            cpa16(kh + off64(r, ch), kgh + (size_t)(k0 + r) * DIM + ch * 8);
            cpa16(kl + off64(r, ch), kgl + (size_t)(k0 + r) * DIM + ch * 8);
        }
        asm volatile("cp.async.commit_group;" ::: "memory");

        // V tile: fp32 load, split, transposed store (V^T[d][key]).
        {
            int key = tid >> 2, ds = (tid & 3) * 16;
            const float* vrow = Vp + (size_t)(b * SEQ + k0 + key) * DIM + h * DH + ds;
#pragma unroll
            for (int f = 0; f < 4; f++) {
                float4 x = *(const float4*)(vrow + f * 4);
                float vv[4] = {x.x, x.y, x.z, x.w};
#pragma unroll
                for (int e = 0; e < 4; e++) {
                    int dd = ds + f * 4 + e;
                    __nv_bfloat16 hi_ = __float2bfloat16_rn(vv[e]);
                    __nv_bfloat16 lo_ = __float2bfloat16_rn(vv[e] - __bfloat162float(hi_));
                    uint32_t off = off64(dd, key >> 3) + (key & 7) * 2;
                    *(__nv_bfloat16*)(smem + 32768 + off) = hi_;
                    *(__nv_bfloat16*)(smem + 40960 + off) = lo_;
                }
            }
        }
        asm volatile("cp.async.wait_group 0;" ::: "memory");
        __syncthreads();

        // S = Q@K^T, 3-term split.
        float s[4][4];
#pragma unroll
        for (int j = 0; j < 4; j++)
#pragma unroll
            for (int q = 0; q < 4; q++) s[j][q] = 0.f;
#pragma unroll
        for (int kk = 0; kk < 4; kk++) {
            int ks8 = kk * 2;
            uint32_t a_h[4], a_l[4], b_h[2][4], b_l[2][4];
            ldsm4(a_h, ldsm_addr64(qh, wm, ks8, lane));
            ldsm4(a_l, ldsm_addr64(ql, wm, ks8, lane));
#pragma unroll
            for (int g = 0; g < 2; g++) {
                ldsm4(b_h[g], ldsm_addr64(kh, wn + g * 16, ks8, lane));
                ldsm4(b_l[g], ldsm_addr64(kl, wn + g * 16, ks8, lane));
            }
#pragma unroll
            for (int j = 0; j < 4; j++) {
                int g = j >> 1, hi = j & 1;
                mma16816(s[j], a_h, b_h[g][hi], b_h[g][2 + hi]);
                mma16816(s[j], a_h, b_l[g][hi], b_l[g][2 + hi]);
                mma16816(s[j], a_l, b_h[g][hi], b_h[g][2 + hi]);
            }
        }

        // P = exp(clamp(S/8))*mask; split to smem; accumulate row sums.
        float p1s = 0.f, p2s = 0.f;
#pragma unroll
        for (int j = 0; j < 4; j++) {
            int col = wn + (lane & 3) * 2 + j * 8;
            float sc, pa, pb, pc, pd;
            sc = fminf(fmaxf(s[j][0] * 0.125f, -50.f), 50.f); pa = __expf(sc) * m1;
            sc = fminf(fmaxf(s[j][1] * 0.125f, -50.f), 50.f); pb = __expf(sc) * m1;
            sc = fminf(fmaxf(s[j][2] * 0.125f, -50.f), 50.f); pc = __expf(sc) * m2;
            sc = fminf(fmaxf(s[j][3] * 0.125f, -50.f), 50.f); pd = __expf(sc) * m2;
            p1s += pa + pb; p2s += pc + pd;
            __nv_bfloat16 pah = __float2bfloat16_rn(pa), pbh = __float2bfloat16_rn(pb);
            __nv_bfloat16 pch = __float2bfloat16_rn(pc), pdh = __float2bfloat16_rn(pd);
            __nv_bfloat16 pal = __float2bfloat16_rn(pa - __bfloat162float(pah));
            __nv_bfloat16 pbl = __float2bfloat16_rn(pb - __bfloat162float(pbh));
            __nv_bfloat16 pcl = __float2bfloat16_rn(pc - __bfloat162float(pch));
            __nv_bfloat16 pdl = __float2bfloat16_rn(pd - __bfloat162float(pdh));
            uint32_t o1 = off64(r1, col >> 3) + (col & 7) * 2;
            uint32_t o2 = off64(r2, col >> 3) + (col & 7) * 2;
            *(__nv_bfloat162*)(smem + 49152 + o1) = __halves2bfloat162(pah, pbh);
            *(__nv_bfloat162*)(smem + 49152 + o2) = __halves2bfloat162(pch, pdh);
            *(__nv_bfloat162*)(smem + 57344 + o1) = __halves2bfloat162(pal, pbl);
            *(__nv_bfloat162*)(smem + 57344 + o2) = __halves2bfloat162(pcl, pdl);
        }
        p1s += __shfl_xor_sync(0xffffffffu, p1s, 1);
        p1s += __shfl_xor_sync(0xffffffffu, p1s, 2);
        p2s += __shfl_xor_sync(0xffffffffu, p2s, 1);
        p2s += __shfl_xor_sync(0xffffffffu, p2s, 2);
        if ((lane & 3) == 0) { dacc1 += p1s; dacc2 += p2s; }
        __syncthreads();

        // O += P@V, 3-term split (B = V^T in smem).
#pragma unroll
        for (int kk = 0; kk < 4; kk++) {
            int ks8 = kk * 2;
            uint32_t a_h[4], a_l[4], b_h[2][4], b_l[2][4];
            ldsm4(a_h, ldsm_addr64(ph, wm, ks8, lane));
            ldsm4(a_l, ldsm_addr64(pl, wm, ks8, lane));
#pragma unroll
            for (int g = 0; g < 2; g++) {
                ldsm4(b_h[g], ldsm_addr64(vh, wn + g * 16, ks8, lane));
                ldsm4(b_l[g], ldsm_addr64(vl, wn + g * 16, ks8, lane));
            }
#pragma unroll
            for (int j = 0; j < 4; j++) {
                int g = j >> 1, hi = j & 1;
                mma16816(o[j], a_h, b_h[g][hi], b_h[g][2 + hi]);
                mma16816(o[j], a_h, b_l[g][hi], b_l[g][2 + hi]);
                mma16816(o[j], a_l, b_h[g][hi], b_h[g][2 + hi]);
            }
        }
    }

    if ((lane & 3) == 0) {
        pden[(wid >> 2) * 64 + r1] = dacc1;
        pden[(wid >> 2) * 64 + r2] = dacc2;
    }
    __syncthreads();
    float dn1 = pden[r1] + pden[64 + r1]; if (dn1 <= 0.f) dn1 = 1.f;
    float dn2 = pden[r2] + pden[64 + r2]; if (dn2 <= 0.f) dn2 = 1.f;
    float i1 = 1.f / dn1, i2 = 1.f / dn2;
#pragma unroll
    for (int j = 0; j < 4; j++) {
        int col = wn + (lane & 3) * 2 + j * 8;
        *(float2*)&Op[(size_t)(b * SEQ + q0 + r1) * DIM + h * DH + col] =
            make_float2(o[j][0] * i1, o[j][1] * i1);
        *(float2*)&Op[(size_t)(b * SEQ + q0 + r2) * DIM + h * DH + col] =
            make_float2(o[j][2] * i2, o[j][3] * i2);
    }
}

// ---------------------------------------------------------------------------
extern "C" void kernel_launch(void* const* d_in, const int* in_sizes, int n_in,
                              void* d_out, int out_size)
{
    const float* Q  = (const float*)d_in[0];
    const float* K  = (const float*)d_in[1];
    const float* V  = (const float*)d_in[2];
    const int*   mask = (const int*)d_in[3];
    const float* Wq = (const float*)d_in[4];
    const float* Wk = (const float*)d_in[5];
    const float* Wv = (const float*)d_in[6];
    const float* Wo = (const float*)d_in[7];
    float* out = (float*)d_out;

    float *gq, *gk, *gv, *ga;
    __nv_bfloat16 *xh, *xl, *wh, *wl, *ath, *atl;
    cudaGetSymbolAddress((void**)&gq,  g_q);
    cudaGetSymbolAddress((void**)&gk,  g_k);
    cudaGetSymbolAddress((void**)&gv,  g_v);
    cudaGetSymbolAddress((void**)&ga,  g_att);
    cudaGetSymbolAddress((void**)&xh,  g_xh);
    cudaGetSymbolAddress((void**)&xl,  g_xl);
    cudaGetSymbolAddress((void**)&wh,  g_wh);
    cudaGetSymbolAddress((void**)&wl,  g_wl);
    cudaGetSymbolAddress((void**)&ath, g_ath);
    cudaGetSymbolAddress((void**)&atl, g_atl);

    cudaFuncSetAttribute(tc_gemm,
                         cudaFuncAttributeMaxDynamicSharedMemorySize, GEMM_SMEM);
    cudaFuncSetAttribute(attn_mma,
                         cudaFuncAttributeMaxDynamicSharedMemorySize, ATT_SMEM);

    // Split inputs + weights to bf16 hi/lo.
    conv4<<<dim3(ND / 1024, 1, 3), 256>>>(Q, K, V, Q, xh, xl, ND);
    conv4<<<dim3(DD / 1024, 1, 4), 256>>>(Wq, Wk, Wv, Wo, wh, wl, DD);

    // Q/K/V projections on tensor cores.
    tc_gemm<<<dim3(8, 32, 3), 256, GEMM_SMEM>>>(xh, xl, wh, wl, gq, gk, gv);

    // Split projected q,k (reuse xh/xl: q at 0, k at ND).
    conv4<<<dim3(ND / 1024, 1, 2), 256>>>(gq, gk, gq, gq, xh, xl, ND);

    // Attention on tensor cores.
    attn_mma<<<dim3(SEQ / 64, NH, NB), 256, ATT_SMEM>>>(xh, xl, gv, mask, ga);

    // Output projection on tensor cores.
    conv4<<<dim3(ND / 1024, 1, 1), 256>>>(ga, ga, ga, ga, ath, atl, ND);
    tc_gemm<<<dim3(8, 32, 1), 256, GEMM_SMEM>>>(ath, atl, wh + 3 * (size_t)DD,
                                                wl + 3 * (size_t)DD, out, out, out);
}